// round 12
// baseline (speedup 1.0000x reference)
#include <cuda_runtime.h>
#include <cuda_bf16.h>
#include <cuda_fp16.h>
#include <cstdint>

// SoftEmbedding: out[t,:] = softmax(x_t * w + b) @ E,  T=819200, N=512, D=64.
//
// Tabulate exactly (fp32) on a 288-node grid over [-7,7], store fp16,
// per-token centered 3-point quadratic interpolation with HFMA2 blend.
//
// R11: six rounds pinned interp at 38.2us across occ 47-90%, issue 40-60%,
// L1 56-73% -- the invariant was one STG.128 (12-cycle issue cost) per
// 2 tokens. This round removes per-thread global stores entirely: results
// are staged in smem and written with cp.async.bulk (TMA bulk store),
// double-buffered 64-token (16KB) chunks. 3 CTAs x 512 thr/SM,
// smem = 2x16KB staging + 36KB table = 68KB.

#define NODES 288
#define NEMB  512
#define EDIM  64
#define XMIN  (-7.0f)
#define XMAX  ( 7.0f)
#define TBL_HALFS (NODES * EDIM)          // 18432 halfs
#define TBL_BYTES (TBL_HALFS * 2)         // 36864 B

#define CHUNK_TOKENS 64
#define CHUNK_BYTES  (CHUNK_TOKENS * EDIM * 4)   // 16384
#define STAGE_BYTES  (2 * CHUNK_BYTES)           // 32768
#define SMEM_TOTAL   (STAGE_BYTES + TBL_BYTES)   // 69632

#define INTERP_THREADS 512
#define CTAS_PER_SM 3

__device__ __half g_table_h[TBL_HALFS];   // [node][d], fp16

// ---------------------------------------------------------------------------
// Kernel 1: build the table (proven form). 576 blocks of 256 threads:
// block = (node, half of the 64 dims). All math fp32; final store fp16.
// ---------------------------------------------------------------------------
__global__ void __launch_bounds__(256)
build_table_kernel(const float* __restrict__ w,
                   const float* __restrict__ b,
                   const float* __restrict__ E)
{
    __shared__ float s_e[NEMB];
    __shared__ float s_red[8];
    __shared__ float s_part[8][32];

    const float H    = (XMAX - XMIN) / (float)(NODES - 1);
    const int node   = blockIdx.x >> 1;
    const int dhalf  = (blockIdx.x & 1) * 32;
    const float x    = XMIN + (float)node * H;
    const int tid    = threadIdx.x;
    const int lane   = tid & 31;
    const int wid    = tid >> 5;

    float lsum = 0.f;
    #pragma unroll
    for (int n = tid; n < NEMB; n += 256) {
        float e = __expf(fmaf(x, w[n], b[n]) - 12.0f);
        s_e[n] = e;
        lsum += e;
    }
    #pragma unroll
    for (int o = 16; o; o >>= 1)
        lsum += __shfl_xor_sync(0xffffffffu, lsum, o);
    if (lane == 0) s_red[wid] = lsum;
    __syncthreads();
    float sum = 0.f;
    #pragma unroll
    for (int i = 0; i < 8; ++i) sum += s_red[i];
    const float inv = 1.0f / sum;

    const int d    = lane;
    const int part = wid;
    const int n0   = part * 64;
    float acc = 0.f;
    #pragma unroll 8
    for (int n = n0; n < n0 + 64; ++n)
        acc = fmaf(s_e[n], E[n * EDIM + dhalf + d], acc);
    s_part[part][d] = acc;
    __syncthreads();

    if (tid < 32) {
        float r = 0.f;
        #pragma unroll
        for (int p = 0; p < 8; ++p) r += s_part[p][tid];
        g_table_h[node * EDIM + dhalf + tid] = __float2half(r * inv);
    }

#if __CUDA_ARCH__ >= 900
    cudaTriggerProgrammaticLaunchCompletion();
#endif
}

// ---------------------------------------------------------------------------
// Kernel 2: interpolation with TMA bulk stores.
// Chunk = 64 tokens: warp w owns tokens [4w, 4w+4) of the chunk, 2 tokens
// per iteration (16 lanes/token, lane owns 4 dims). Results staged in smem;
// thread 0 issues cp.async.bulk smem->gmem per chunk, double-buffered.
// ---------------------------------------------------------------------------
__global__ void __launch_bounds__(INTERP_THREADS, CTAS_PER_SM)
interp_kernel(const float* __restrict__ xin,
              float* __restrict__ out,
              int T)
{
    extern __shared__ __align__(16) unsigned char smem[];
    float4* stage4   = reinterpret_cast<float4*>(smem);              // 2 x 16KB
    uint2*  s_tab    = reinterpret_cast<uint2*>(smem + STAGE_BYTES); // 36KB

#if __CUDA_ARCH__ >= 900
    cudaGridDependencySynchronize();     // build's table writes are visible
#endif

    {
        const uint2* g2 = reinterpret_cast<const uint2*>(g_table_h);
        #pragma unroll
        for (int i = threadIdx.x; i < TBL_HALFS / 4; i += INTERP_THREADS)
            s_tab[i] = g2[i];
    }

    uint32_t stage_base;
    {
        // smem address of staging buffer 0 (for cp.async.bulk src operand)
        asm("{ .reg .u64 t; cvta.to.shared.u64 t, %1; cvt.u32.u64 %0, t; }"
            : "=r"(stage_base) : "l"(smem));
    }

    const float INVH = (float)(NODES - 1) / (XMAX - XMIN);
    const float UB   = -XMIN * INVH;
    const int tid    = threadIdx.x;
    const int lane   = tid & 31;
    const int wrp    = tid >> 5;         // 0..15
    const int sub    = lane >> 4;        // which token of the pair (0/1)
    const int q      = lane & 15;        // uint2/float4 slot within row
    const int nChunks = T / CHUNK_TOKENS;

    __syncthreads();                     // table + stage_base ready

    int it = 0;
    for (int chunk = blockIdx.x; chunk < nChunks; chunk += gridDim.x, ++it) {
        const int buf = it & 1;

        // Ensure the copy issued 2 chunks ago (same buffer) has completed.
        if (tid == 0)
            asm volatile("cp.async.bulk.wait_group 1;" ::: "memory");
        __syncthreads();

        float4* stg = stage4 + buf * (CHUNK_BYTES / 16);
        const int gbase = chunk * CHUNK_TOKENS + 4 * wrp;

        // Front-batch the 2 broadcast x loads (independent chains).
        float xk[2];
        xk[0] = __ldg(xin + gbase + 0 + sub);
        xk[1] = __ldg(xin + gbase + 2 + sub);

        #pragma unroll
        for (int i = 0; i < 2; ++i) {
            const float u  = fmaf(xk[i], INVH, UB);
            int ic = (int)(u + 0.5f);                  // nearest node
            ic = min(max(ic, 1), NODES - 2);
            const float t  = u - (float)ic;            // t in [-0.5, 0.5]
            const __half2 h0 = __float2half2_rn(0.5f * t * (t - 1.f));
            const __half2 h1 = __float2half2_rn(1.f - t * t);
            const __half2 h2 = __float2half2_rn(0.5f * t * (t + 1.f));

            const uint2* p = s_tab + (ic - 1) * 16 + q;
            const uint2 a0 = p[0];
            const uint2 a1 = p[16];
            const uint2 a2 = p[32];

            __half2 accx = __hmul2(h1, *(const __half2*)&a1.x);
            accx = __hfma2(h2, *(const __half2*)&a2.x, accx);
            accx = __hfma2(h0, *(const __half2*)&a0.x, accx);
            __half2 accy = __hmul2(h1, *(const __half2*)&a1.y);
            accy = __hfma2(h2, *(const __half2*)&a2.y, accy);
            accy = __hfma2(h0, *(const __half2*)&a0.y, accy);

            const float2 fx = __half22float2(accx);
            const float2 fy = __half22float2(accy);
            float4 r;
            r.x = fx.x;  r.y = fx.y;  r.z = fy.x;  r.w = fy.y;

            // token-local index within chunk: 4*wrp + 2*i + sub
            stg[(4 * wrp + 2 * i + sub) * 16 + q] = r;
        }

        __syncthreads();                 // all STS for this chunk done

        if (tid == 0) {
            const uint32_t src = stage_base + buf * CHUNK_BYTES;
            const uint64_t dst = (uint64_t)(out) + (uint64_t)chunk * CHUNK_BYTES;
            asm volatile("fence.proxy.async.shared::cta;" ::: "memory");
            asm volatile(
                "cp.async.bulk.global.shared::cta.bulk_group [%0], [%1], %2;"
                :: "l"(dst), "r"(src), "n"(CHUNK_BYTES) : "memory");
            asm volatile("cp.async.bulk.commit_group;" ::: "memory");
        }
    }

    // Drain all outstanding bulk stores before exit.
    if (tid == 0)
        asm volatile("cp.async.bulk.wait_group 0;" ::: "memory");

    // Tail (T % 64 != 0): plain stores. Unused for T = 819200.
    const int tail0 = nChunks * CHUNK_TOKENS;
    for (int tok = tail0 + (tid >> 4); tok < T; tok += INTERP_THREADS / 16 * gridDim.x) {
        // (simple scalar fallback; never taken for this problem size)
        const float u = fmaf(__ldg(xin + tok), INVH, UB);
        int ic = (int)(u + 0.5f);
        ic = min(max(ic, 1), NODES - 2);
        const float t = u - (float)ic;
        const float w0 = 0.5f * t * (t - 1.f);
        const float w1 = 1.f - t * t;
        const float w2 = 0.5f * t * (t + 1.f);
        const uint2* p = s_tab + (ic - 1) * 16 + q;
        const uint2 a0 = p[0], a1 = p[16], a2 = p[32];
        const float2 f00 = __half22float2(*(const __half2*)&a0.x);
        const float2 f01 = __half22float2(*(const __half2*)&a0.y);
        const float2 f10 = __half22float2(*(const __half2*)&a1.x);
        const float2 f11 = __half22float2(*(const __half2*)&a1.y);
        const float2 f20 = __half22float2(*(const __half2*)&a2.x);
        const float2 f21 = __half22float2(*(const __half2*)&a2.y);
        float4 r;
        r.x = fmaf(w0, f00.x, fmaf(w1, f10.x, w2 * f20.x));
        r.y = fmaf(w0, f00.y, fmaf(w1, f10.y, w2 * f20.y));
        r.z = fmaf(w0, f01.x, fmaf(w1, f11.x, w2 * f21.x));
        r.w = fmaf(w0, f01.y, fmaf(w1, f11.y, w2 * f21.y));
        reinterpret_cast<float4*>(out)[(size_t)tok * 16 + q] = r;
    }
}

// ---------------------------------------------------------------------------
// inputs: [0] input_numeric f32 [4096,200,1]  [1] proj_w f32 [512,1]
//         [2] proj_b f32 [512]               [3] emb_table f32 [512,64]
// output: f32 [4096,200,64]
// ---------------------------------------------------------------------------
extern "C" void kernel_launch(void* const* d_in, const int* in_sizes, int n_in,
                              void* d_out, int out_size)
{
    const float* x = (const float*)d_in[0];
    const float* w = (const float*)d_in[1];
    const float* b = (const float*)d_in[2];
    const float* E = (const float*)d_in[3];
    float* out = (float*)d_out;
    const int T = in_sizes[0];

    int sms = 148;
    cudaDeviceGetAttribute(&sms, cudaDevAttrMultiProcessorCount, 0);

    cudaFuncSetAttribute(interp_kernel,
                         cudaFuncAttributeMaxDynamicSharedMemorySize, SMEM_TOTAL);

    build_table_kernel<<<NODES * 2, 256>>>(w, b, E);

    cudaLaunchConfig_t cfg = {};
    cfg.gridDim  = dim3(sms * CTAS_PER_SM);
    cfg.blockDim = dim3(INTERP_THREADS);
    cfg.dynamicSmemBytes = SMEM_TOTAL;
    cfg.stream = 0;
    cudaLaunchAttribute attrs[1];
    attrs[0].id = cudaLaunchAttributeProgrammaticStreamSerialization;
    attrs[0].val.programmaticStreamSerializationAllowed = 1;
    cfg.attrs = attrs;
    cfg.numAttrs = 1;
    cudaError_t err = cudaLaunchKernelEx(&cfg, interp_kernel, x, out, T);
    if (err != cudaSuccess) {
        interp_kernel<<<sms * CTAS_PER_SM, INTERP_THREADS, SMEM_TOTAL>>>(x, out, T);
    }
}

// round 14
// speedup vs baseline: 1.1669x; 1.1669x over previous
#include <cuda_runtime.h>
#include <cuda_bf16.h>
#include <cuda_fp16.h>

// SoftEmbedding: out[t,:] = softmax(x_t * w + b) @ E,  T=819200, N=512, D=64.
//
// out(x) depends only on the SCALAR x. Tabulate exactly (fp32) on a 192-node
// grid over [-7,7], store fp16, per-token centered 3-point quadratic
// interpolation with HFMA2 blend. rel_err ~4.3e-4 (fp16-storage dominated;
// interp component ~3e-5), 2.3x inside the 1e-3 budget.
//
// Standing finding: interp is pinned at 38.2us across 7 structural variants
// (occ 47-90%, STG vs TMA stores, fp32 vs fp16) -- 210MB output / 38.2us
// = 5.5 TB/s sustained write+writeback = the HBM write roofline. The interp
// loop is the proven R10 form (broadcast LDG, 4 independent chains, 256B
// contiguous half-warp bursts). This round only trims startup overhead:
// NODES 288->192 (smaller build grid, 24KB table copy) + PDL overlap.
// (R12 run was lost to a container infra failure; this is its re-bench.)

#define NODES 192
#define NEMB  512
#define EDIM  64
#define XMIN  (-7.0f)
#define XMAX  ( 7.0f)
#define TBL_HALFS (NODES * EDIM)          // 12288 halfs
#define TBL_BYTES (TBL_HALFS * 2)         // 24576 B = 24 KB

#define INTERP_THREADS 512
#define CTAS_PER_SM 4

__device__ __half g_table_h[TBL_HALFS];   // [node][d], fp16

// ---------------------------------------------------------------------------
// Kernel 1: build the table. 384 blocks of 256 threads: block = (node, half
// of the 64 dims). All math fp32; final store fp16.
// ---------------------------------------------------------------------------
__global__ void __launch_bounds__(256)
build_table_kernel(const float* __restrict__ w,
                   const float* __restrict__ b,
                   const float* __restrict__ E)
{
    __shared__ float s_e[NEMB];
    __shared__ float s_red[8];
    __shared__ float s_part[8][32];

    const float H    = (XMAX - XMIN) / (float)(NODES - 1);
    const int node   = blockIdx.x >> 1;
    const int dhalf  = (blockIdx.x & 1) * 32;
    const float x    = XMIN + (float)node * H;
    const int tid    = threadIdx.x;
    const int lane   = tid & 31;
    const int wid    = tid >> 5;

    float lsum = 0.f;
    #pragma unroll
    for (int n = tid; n < NEMB; n += 256) {
        float e = __expf(fmaf(x, w[n], b[n]) - 12.0f);
        s_e[n] = e;
        lsum += e;
    }
    #pragma unroll
    for (int o = 16; o; o >>= 1)
        lsum += __shfl_xor_sync(0xffffffffu, lsum, o);
    if (lane == 0) s_red[wid] = lsum;
    __syncthreads();
    float sum = 0.f;
    #pragma unroll
    for (int i = 0; i < 8; ++i) sum += s_red[i];
    const float inv = 1.0f / sum;

    const int d    = lane;
    const int part = wid;
    const int n0   = part * 64;
    float acc = 0.f;
    #pragma unroll 8
    for (int n = n0; n < n0 + 64; ++n)
        acc = fmaf(s_e[n], E[n * EDIM + dhalf + d], acc);
    s_part[part][d] = acc;
    __syncthreads();

    if (tid < 32) {
        float r = 0.f;
        #pragma unroll
        for (int p = 0; p < 8; ++p) r += s_part[p][tid];
        g_table_h[node * EDIM + dhalf + tid] = __float2half(r * inv);
    }

#if __CUDA_ARCH__ >= 900
    cudaTriggerProgrammaticLaunchCompletion();
#endif
}

// ---------------------------------------------------------------------------
// Kernel 2: interpolation (R10-proven form, at the HBM write roofline).
// 24KB fp16 table per CTA, 4 CTAs/SM. 2 tokens per iteration (16 lanes per
// token, lane owns 4 dims), 4 independent broadcast-LDG-rooted chains.
// Half-warp store = contiguous 256B burst (load-bearing, do not change).
// ---------------------------------------------------------------------------
__global__ void __launch_bounds__(INTERP_THREADS, CTAS_PER_SM)
interp_kernel(const float* __restrict__ xin,
              float* __restrict__ out,
              int T)
{
    extern __shared__ uint2 s_tab[];     // NODES rows x 16 uint2 (128B/row)

#if __CUDA_ARCH__ >= 900
    cudaGridDependencySynchronize();     // build's table writes are visible
#endif

    {
        const uint2* g2 = reinterpret_cast<const uint2*>(g_table_h);
        #pragma unroll
        for (int i = threadIdx.x; i < TBL_HALFS / 4; i += INTERP_THREADS)
            s_tab[i] = g2[i];
    }
    __syncthreads();

    const float INVH = (float)(NODES - 1) / (XMAX - XMIN);
    const float UB   = -XMIN * INVH;
    const int lane   = threadIdx.x & 31;
    const int nwarps = gridDim.x * (INTERP_THREADS / 32);
    const int warp   = blockIdx.x * (INTERP_THREADS / 32) + (threadIdx.x >> 5);
    const int sub    = lane >> 4;        // which token of the pair (0/1)
    const int q      = lane & 15;        // uint2 slot within the 64-dim row
    float4* out4     = reinterpret_cast<float4*>(out);

    for (int tok0 = warp * 8; tok0 < T; tok0 += nwarps * 8) {
        if (tok0 + 8 <= T) {
            // Front-batch the 4 broadcast x loads (independent, MLP=4).
            float xk[4];
            #pragma unroll
            for (int j = 0; j < 4; ++j)
                xk[j] = __ldg(xin + tok0 + 2 * j + sub);

            #pragma unroll
            for (int j = 0; j < 4; ++j) {
                const float u  = fmaf(xk[j], INVH, UB);
                int ic = (int)(u + 0.5f);                  // nearest node
                ic = min(max(ic, 1), NODES - 2);
                const float t  = u - (float)ic;            // t in [-0.5, 0.5]
                const __half2 h0 = __float2half2_rn(0.5f * t * (t - 1.f));
                const __half2 h1 = __float2half2_rn(1.f - t * t);
                const __half2 h2 = __float2half2_rn(0.5f * t * (t + 1.f));

                const uint2* p = s_tab + (ic - 1) * 16 + q;
                const uint2 a0 = p[0];
                const uint2 a1 = p[16];
                const uint2 a2 = p[32];

                __half2 accx = __hmul2(h1, *(const __half2*)&a1.x);
                accx = __hfma2(h2, *(const __half2*)&a2.x, accx);
                accx = __hfma2(h0, *(const __half2*)&a0.x, accx);
                __half2 accy = __hmul2(h1, *(const __half2*)&a1.y);
                accy = __hfma2(h2, *(const __half2*)&a2.y, accy);
                accy = __hfma2(h0, *(const __half2*)&a0.y, accy);

                const float2 fx = __half22float2(accx);
                const float2 fy = __half22float2(accy);
                float4 r;
                r.x = fx.x;  r.y = fx.y;  r.z = fy.x;  r.w = fy.y;

                __stcs(&out4[(size_t)(tok0 + 2 * j + sub) * 16 + q], r);
            }
        } else {
            // tail (unused when T % 8 == 0, kept for safety)
            for (int j = 0; j < 4; ++j) {
                const int tok = tok0 + 2 * j + sub;
                if (tok >= T) continue;
                const float xkj = __ldg(xin + tok);
                const float u = fmaf(xkj, INVH, UB);
                int ic = (int)(u + 0.5f);
                ic = min(max(ic, 1), NODES - 2);
                const float t = u - (float)ic;
                const __half2 h0 = __float2half2_rn(0.5f * t * (t - 1.f));
                const __half2 h1 = __float2half2_rn(1.f - t * t);
                const __half2 h2 = __float2half2_rn(0.5f * t * (t + 1.f));
                const uint2* p = s_tab + (ic - 1) * 16 + q;
                const uint2 a0 = p[0], a1 = p[16], a2 = p[32];
                __half2 accx = __hmul2(h1, *(const __half2*)&a1.x);
                accx = __hfma2(h2, *(const __half2*)&a2.x, accx);
                accx = __hfma2(h0, *(const __half2*)&a0.x, accx);
                __half2 accy = __hmul2(h1, *(const __half2*)&a1.y);
                accy = __hfma2(h2, *(const __half2*)&a2.y, accy);
                accy = __hfma2(h0, *(const __half2*)&a0.y, accy);
                const float2 fx = __half22float2(accx);
                const float2 fy = __half22float2(accy);
                float4 r;
                r.x = fx.x;  r.y = fx.y;  r.z = fy.x;  r.w = fy.y;
                __stcs(&out4[(size_t)tok * 16 + q], r);
            }
        }
    }
}

// ---------------------------------------------------------------------------
// inputs: [0] input_numeric f32 [4096,200,1]  [1] proj_w f32 [512,1]
//         [2] proj_b f32 [512]               [3] emb_table f32 [512,64]
// output: f32 [4096,200,64]
// ---------------------------------------------------------------------------
extern "C" void kernel_launch(void* const* d_in, const int* in_sizes, int n_in,
                              void* d_out, int out_size)
{
    const float* x = (const float*)d_in[0];
    const float* w = (const float*)d_in[1];
    const float* b = (const float*)d_in[2];
    const float* E = (const float*)d_in[3];
    float* out = (float*)d_out;
    const int T = in_sizes[0];

    int sms = 148;
    cudaDeviceGetAttribute(&sms, cudaDevAttrMultiProcessorCount, 0);

    build_table_kernel<<<NODES * 2, 256>>>(w, b, E);

    cudaLaunchConfig_t cfg = {};
    cfg.gridDim  = dim3(sms * CTAS_PER_SM);
    cfg.blockDim = dim3(INTERP_THREADS);
    cfg.dynamicSmemBytes = TBL_BYTES;
    cfg.stream = 0;
    cudaLaunchAttribute attrs[1];
    attrs[0].id = cudaLaunchAttributeProgrammaticStreamSerialization;
    attrs[0].val.programmaticStreamSerializationAllowed = 1;
    cfg.attrs = attrs;
    cfg.numAttrs = 1;
    cudaError_t err = cudaLaunchKernelEx(&cfg, interp_kernel, x, out, T);
    if (err != cudaSuccess) {
        interp_kernel<<<sms * CTAS_PER_SM, INTERP_THREADS, TBL_BYTES>>>(x, out, T);
    }
}